// round 1
// baseline (speedup 1.0000x reference)
#include <cuda_runtime.h>
#include <cooperative_groups.h>

namespace cg = cooperative_groups;

#define T_STEPS 2048
#define V_SZ    2048
#define G_SZ    24
#define K_SZ    512
#define CLUSTER_N 8
#define JPB     64              // columns of Wh per CTA = K_SZ / CLUSTER_N
#define RPC     3               // recurrences per cluster
#define NCLUSTERS 16            // 16 * 3 = 48 recurrences = 24 groups * 2 dirs
#define NBLOCKS (NCLUSTERS * CLUSTER_N)

// SMEM layout (floats / float4s), total bytes:
//   Wh_s : 512*64 floats      = 131072 B
//   h4   : 2 * 512 float4     =  16384 B
//   part : 8 * 64 float4      =   8192 B
//   x4   : 2 * 64 float4      =   2048 B
#define SMEM_BYTES (K_SZ*JPB*4 + 2*K_SZ*16 + 8*64*16 + 2*64*16)

// Scratch (no cudaMalloc allowed)
__device__ float g_P[V_SZ * K_SZ];       // P = W_e @ Wx + b   (V, K)
__device__ int   g_idx[T_STEPS * G_SZ];  // idx[t,g] = perms[g, token_t]

// ---------------------------------------------------------------------------
// Kernel 1: recover tokens from one-hot rows and build the gather index table
// ---------------------------------------------------------------------------
__global__ void token_kernel(const float* __restrict__ seq,
                             const int* __restrict__ perms) {
    int t = blockIdx.x;
    __shared__ int tok;
    const float* row = seq + (size_t)t * V_SZ;
    for (int v = threadIdx.x; v < V_SZ; v += blockDim.x)
        if (row[v] > 0.5f) tok = v;     // exactly one writer (exact one-hot)
    __syncthreads();
    if (threadIdx.x < G_SZ)
        g_idx[t * G_SZ + threadIdx.x] = perms[threadIdx.x * V_SZ + tok];
}

// ---------------------------------------------------------------------------
// Kernel 2: P = W_e @ Wx + b  (2048x512 @ 512x512), simple SMEM-tiled fp32 GEMM
// ---------------------------------------------------------------------------
__global__ void __launch_bounds__(256)
gemm_P_kernel(const float* __restrict__ We,
              const float* __restrict__ Wx,
              const float* __restrict__ b) {
    __shared__ float sA[64][17];
    __shared__ float sB[16][68];
    int tid = threadIdx.x;
    int tx = tid & 15, ty = tid >> 4;
    int row0 = blockIdx.y * 64;   // V dim
    int col0 = blockIdx.x * 64;   // K dim
    float acc[4][4] = {};

    for (int kc = 0; kc < K_SZ; kc += 16) {
        {
            int v  = tid >> 2;
            int c4 = (tid & 3) * 4;
            float4 av = *(const float4*)&We[(size_t)(row0 + v) * K_SZ + kc + c4];
            sA[v][c4 + 0] = av.x; sA[v][c4 + 1] = av.y;
            sA[v][c4 + 2] = av.z; sA[v][c4 + 3] = av.w;
        }
        {
            int c  = tid >> 4;
            int k4 = (tid & 15) * 4;
            float4 bv = *(const float4*)&Wx[(size_t)(kc + c) * K_SZ + col0 + k4];
            sB[c][k4 + 0] = bv.x; sB[c][k4 + 1] = bv.y;
            sB[c][k4 + 2] = bv.z; sB[c][k4 + 3] = bv.w;
        }
        __syncthreads();
        #pragma unroll
        for (int cc = 0; cc < 16; cc++) {
            float ar[4], br[4];
            #pragma unroll
            for (int u = 0; u < 4; u++) ar[u] = sA[ty * 4 + u][cc];
            #pragma unroll
            for (int w = 0; w < 4; w++) br[w] = sB[cc][tx * 4 + w];
            #pragma unroll
            for (int u = 0; u < 4; u++)
                #pragma unroll
                for (int w = 0; w < 4; w++)
                    acc[u][w] = fmaf(ar[u], br[w], acc[u][w]);
        }
        __syncthreads();
    }
    #pragma unroll
    for (int u = 0; u < 4; u++) {
        int r = row0 + ty * 4 + u;
        #pragma unroll
        for (int w = 0; w < 4; w++) {
            int c = col0 + tx * 4 + w;
            g_P[(size_t)r * K_SZ + c] = acc[u][w] + b[c];
        }
    }
}

// ---------------------------------------------------------------------------
// Kernel 3: persistent cluster-cooperative recurrence.
// Cluster of 8 CTAs; CTA `rank` owns Wh columns [rank*64, rank*64+64) in SMEM
// and 3 recurrences (group/direction). Per step it computes its 64 output
// columns for all 3 recurrences, tanh+x, writes global output, and DSMEM-
// scatters the packed float4 (r0,r1,r2,0) into every rank's next-h buffer.
// One cluster.sync per step (double-buffered h).
// ---------------------------------------------------------------------------
__device__ __forceinline__ int tpos(int s, int dir) {
    // scan-step -> time index (source AND destination coincide for both dirs)
    return dir ? ((s < T_STEPS - 1) ? (T_STEPS - 2 - s) : (T_STEPS - 1)) : s;
}

extern __shared__ float smem_dyn[];

__global__ void __launch_bounds__(512, 1) __cluster_dims__(CLUSTER_N, 1, 1)
rnn_kernel(const float* __restrict__ Wh,
           float* __restrict__ out,
           int writeHt) {
    cg::cluster_group cluster = cg::this_cluster();
    const int rank = (int)cluster.block_rank();
    const int cid  = blockIdx.x / CLUSTER_N;
    const int tid  = threadIdx.x;
    const int j    = tid & 63;
    const int seg  = tid >> 6;          // 0..7
    const int jg   = rank * JPB;        // global column base

    float*  Wh_s = smem_dyn;                          // [512*64]
    float4* h4   = (float4*)(smem_dyn + K_SZ * JPB);  // [2][512]
    float4* part = h4 + 2 * K_SZ;                     // [8*64]
    float4* x4   = part + 8 * 64;                     // [2*64]

    // the 3 recurrences of this cluster
    const int r0 = cid * RPC + 0, r1 = cid * RPC + 1, r2 = cid * RPC + 2;
    const int g0 = r0 >> 1, d0 = r0 & 1;
    const int g1 = r1 >> 1, d1 = r1 & 1;
    const int g2 = r2 >> 1, d2 = r2 & 1;

    // load Wh column slice: Wh_s[i*64 + jj] = Wh[i*512 + jg + jj]
    for (int idx = tid; idx < K_SZ * JPB; idx += 512) {
        int i = idx >> 6, jj = idx & 63;
        Wh_s[idx] = Wh[(size_t)i * K_SZ + jg + jj];
    }
    // h0 = 0
    for (int i = tid; i < K_SZ; i += 512)
        h4[i] = make_float4(0.f, 0.f, 0.f, 0.f);
    // prefetch x for step 0 into buffer 0
    if (tid < 64) {
        float4 xv;
        xv.x = g_P[(size_t)g_idx[tpos(0, d0) * G_SZ + g0] * K_SZ + jg + j];
        xv.y = g_P[(size_t)g_idx[tpos(0, d1) * G_SZ + g1] * K_SZ + jg + j];
        xv.z = g_P[(size_t)g_idx[tpos(0, d2) * G_SZ + g2] * K_SZ + jg + j];
        xv.w = 0.f;
        x4[j] = xv;
    }
    __syncthreads();
    cluster.sync();

    int p = 0;
    for (int s = 0; s < T_STEPS; s++) {
        // ---- phase 1: partial dot products over this thread's i-segment ----
        const float4* hb = h4 + p * K_SZ;
        float a0 = 0.f, a1 = 0.f, a2 = 0.f;
        const int ib = seg * 64;
        #pragma unroll 8
        for (int ii = 0; ii < 64; ii++) {
            float4 hv = hb[ib + ii];                    // broadcast LDS.128
            float  w  = Wh_s[(ib + ii) * 64 + j];       // conflict-free LDS.32
            a0 = fmaf(hv.x, w, a0);
            a1 = fmaf(hv.y, w, a1);
            a2 = fmaf(hv.z, w, a2);
        }
        part[seg * 64 + j] = make_float4(a0, a1, a2, 0.f);
        __syncthreads();

        // ---- phase 2: reduce, tanh, write out, DSMEM all-gather ----
        if (tid < 64) {
            float s0 = 0.f, s1 = 0.f, s2 = 0.f;
            #pragma unroll
            for (int q = 0; q < 8; q++) {
                float4 v = part[q * 64 + j];
                s0 += v.x; s1 += v.y; s2 += v.z;
            }
            float4 xv = x4[p * 64 + j];
            float v0 = tanhf(s0 + xv.x);
            float v1 = tanhf(s1 + xv.y);
            float v2 = tanhf(s2 + xv.z);

            int t0 = tpos(s, d0), t1 = tpos(s, d1), t2 = tpos(s, d2);
            out[((size_t)t0 * G_SZ + g0) * (2 * K_SZ) + d0 * K_SZ + jg + j] = v0;
            out[((size_t)t1 * G_SZ + g1) * (2 * K_SZ) + d1 * K_SZ + jg + j] = v1;
            out[((size_t)t2 * G_SZ + g2) * (2 * K_SZ) + d2 * K_SZ + jg + j] = v2;
            if (s == T_STEPS - 1 && writeHt) {
                size_t hb0 = (size_t)T_STEPS * G_SZ * 2 * K_SZ;
                out[hb0 + (size_t)g0 * (2 * K_SZ) + d0 * K_SZ + jg + j] = v0;
                out[hb0 + (size_t)g1 * (2 * K_SZ) + d1 * K_SZ + jg + j] = v1;
                out[hb0 + (size_t)g2 * (2 * K_SZ) + d2 * K_SZ + jg + j] = v2;
            }

            float4 hval = make_float4(v0, v1, v2, 0.f);
            float4* nxt = h4 + (1 - p) * K_SZ + (jg + j);
            #pragma unroll
            for (int rk = 0; rk < CLUSTER_N; rk++) {
                float4* dst = cluster.map_shared_rank(nxt, rk);
                *dst = hval;
            }
        } else if (tid < 128) {
            // ---- prefetch x for step s+1 (hidden behind phase 2 + sync) ----
            int sn = s + 1;
            if (sn < T_STEPS) {
                int jj = tid - 64;
                float4 xv;
                xv.x = g_P[(size_t)g_idx[tpos(sn, d0) * G_SZ + g0] * K_SZ + jg + jj];
                xv.y = g_P[(size_t)g_idx[tpos(sn, d1) * G_SZ + g1] * K_SZ + jg + jj];
                xv.z = g_P[(size_t)g_idx[tpos(sn, d2) * G_SZ + g2] * K_SZ + jg + jj];
                xv.w = 0.f;
                x4[(1 - p) * 64 + jj] = xv;
            }
        }
        cluster.sync();   // DSMEM writes visible; safe to flip buffers
        p ^= 1;
    }
}

// ---------------------------------------------------------------------------
extern "C" void kernel_launch(void* const* d_in, const int* in_sizes, int n_in,
                              void* d_out, int out_size) {
    const float* seq   = (const float*)d_in[0];  // (T, V)
    const int*   perms = (const int*)  d_in[1];  // (G, V)
    const float* We    = (const float*)d_in[2];  // (V, K)
    const float* Wx    = (const float*)d_in[3];  // (K, K)
    const float* Wh    = (const float*)d_in[4];  // (K, K)
    const float* b     = (const float*)d_in[5];  // (K,)
    float* out = (float*)d_out;
    (void)in_sizes; (void)n_in;

    // write ht block only if the output buffer includes it
    long long need = (long long)T_STEPS * G_SZ * 2 * K_SZ + (long long)G_SZ * 2 * K_SZ;
    int writeHt = ((long long)out_size >= need) ? 1 : 0;

    cudaFuncSetAttribute(rnn_kernel,
                         cudaFuncAttributeMaxDynamicSharedMemorySize, SMEM_BYTES);

    token_kernel<<<T_STEPS, 256>>>(seq, perms);
    dim3 ggrid(K_SZ / 64, V_SZ / 64);
    gemm_P_kernel<<<ggrid, 256>>>(We, Wx, b);
    rnn_kernel<<<NBLOCKS, 512, SMEM_BYTES>>>(Wh, out, writeHt);
}

// round 2
// speedup vs baseline: 2.1215x; 2.1215x over previous
#include <cuda_runtime.h>
#include <cooperative_groups.h>
#include <cstdint>

namespace cg = cooperative_groups;

#define T_STEPS 2048
#define V_SZ    2048
#define G_SZ    24
#define K_SZ    512
#define CLUSTER_N 8
#define JPB     64              // columns of Wh per CTA
#define NCLUSTERS 16            // 16 clusters * 3 recurrences = 48
#define NBLOCKS (NCLUSTERS * CLUSTER_N)
#define THREADS_RNN 256

// ---------------- mbarrier / async helpers ----------------
#define MBARRIER_INIT(addr, count) \
    asm volatile("mbarrier.init.shared.b64 [%0], %1;" :: "r"((uint32_t)(addr)), "r"((uint32_t)(count)) : "memory")

#define MBARRIER_EXPECT_TX(addr, bytes) \
    asm volatile("mbarrier.arrive.expect_tx.shared.b64 _, [%0], %1;" :: "r"((uint32_t)(addr)), "r"((uint32_t)(bytes)) : "memory")

#define MBARRIER_WAIT_PARITY(mbar_smem_addr, phase_parity) do { \
    uint32_t _mbar = (uint32_t)(mbar_smem_addr); \
    uint32_t _parity = (uint32_t)(phase_parity); \
    uint32_t _done; \
    asm volatile( \
        "{\n\t" \
        ".reg .pred p;\n\t" \
        "mbarrier.try_wait.parity.acquire.cta.shared::cta.b64 p, [%1], %2;\n\t" \
        "selp.b32 %0, 1, 0, p;\n\t" \
        "}" \
        : "=r"(_done) : "r"(_mbar), "r"(_parity) : "memory"); \
    if (!_done) { \
        asm volatile( \
            "{\n\t" \
            ".reg .pred P1;\n\t" \
            "WAIT_LOOP_%=:\n\t" \
            "mbarrier.try_wait.parity.acquire.cta.shared::cta.b64 P1, [%0], %1, 0x989680;\n\t" \
            "@P1 bra.uni WAIT_DONE_%=;\n\t" \
            "bra.uni WAIT_LOOP_%=;\n\t" \
            "WAIT_DONE_%=:\n\t" \
            "}" \
            :: "r"(_mbar), "r"(_parity) : "memory"); \
    } \
} while(0)

__device__ __forceinline__ uint32_t s2u(const void* p) {
    uint32_t a;
    asm("{ .reg .u64 t; cvta.to.shared.u64 t, %1; cvt.u32.u64 %0, t; }" : "=r"(a) : "l"(p));
    return a;
}

// Scratch (no cudaMalloc allowed)
__device__ float g_P[V_SZ * K_SZ];       // P = W_e @ Wx + b   (V, K)
__device__ int   g_idx[T_STEPS * G_SZ];  // idx[t,g] = perms[g, token_t]

// ---------------------------------------------------------------------------
// Kernel 1: recover tokens from one-hot rows, build gather index table
// ---------------------------------------------------------------------------
__global__ void token_kernel(const float* __restrict__ seq,
                             const int* __restrict__ perms) {
    int t = blockIdx.x;
    __shared__ int tok;
    const float* row = seq + (size_t)t * V_SZ;
    for (int v = threadIdx.x; v < V_SZ; v += blockDim.x)
        if (row[v] > 0.5f) tok = v;
    __syncthreads();
    if (threadIdx.x < G_SZ)
        g_idx[t * G_SZ + threadIdx.x] = perms[threadIdx.x * V_SZ + tok];
}

// ---------------------------------------------------------------------------
// Kernel 2: P = W_e @ Wx + b  (2048x512 @ 512x512)
// ---------------------------------------------------------------------------
__global__ void __launch_bounds__(256)
gemm_P_kernel(const float* __restrict__ We,
              const float* __restrict__ Wx,
              const float* __restrict__ b) {
    __shared__ float sA[64][17];
    __shared__ float sB[16][68];
    int tid = threadIdx.x;
    int tx = tid & 15, ty = tid >> 4;
    int row0 = blockIdx.y * 64;
    int col0 = blockIdx.x * 64;
    float acc[4][4] = {};

    for (int kc = 0; kc < K_SZ; kc += 16) {
        {
            int v  = tid >> 2;
            int c4 = (tid & 3) * 4;
            float4 av = *(const float4*)&We[(size_t)(row0 + v) * K_SZ + kc + c4];
            sA[v][c4 + 0] = av.x; sA[v][c4 + 1] = av.y;
            sA[v][c4 + 2] = av.z; sA[v][c4 + 3] = av.w;
        }
        {
            int c  = tid >> 4;
            int k4 = (tid & 15) * 4;
            float4 bv = *(const float4*)&Wx[(size_t)(kc + c) * K_SZ + col0 + k4];
            sB[c][k4 + 0] = bv.x; sB[c][k4 + 1] = bv.y;
            sB[c][k4 + 2] = bv.z; sB[c][k4 + 3] = bv.w;
        }
        __syncthreads();
        #pragma unroll
        for (int cc = 0; cc < 16; cc++) {
            float ar[4], br[4];
            #pragma unroll
            for (int u = 0; u < 4; u++) ar[u] = sA[ty * 4 + u][cc];
            #pragma unroll
            for (int w = 0; w < 4; w++) br[w] = sB[cc][tx * 4 + w];
            #pragma unroll
            for (int u = 0; u < 4; u++)
                #pragma unroll
                for (int w = 0; w < 4; w++)
                    acc[u][w] = fmaf(ar[u], br[w], acc[u][w]);
        }
        __syncthreads();
    }
    #pragma unroll
    for (int u = 0; u < 4; u++) {
        int r = row0 + ty * 4 + u;
        #pragma unroll
        for (int w = 0; w < 4; w++) {
            int c = col0 + tx * 4 + w;
            g_P[(size_t)r * K_SZ + c] = acc[u][w] + b[c];
        }
    }
}

// ---------------------------------------------------------------------------
// Kernel 3: persistent cluster recurrence, Wh in registers, mbarrier DSMEM.
// 256 threads = 32 lanes x 8 segs. Thread (seg, lane) owns Wh columns
// (jg+lane, jg+lane+32) restricted to rows [seg*64, seg*64+64), in registers.
// ---------------------------------------------------------------------------
__device__ __forceinline__ int tpos(int s, int dir) {
    return dir ? ((s < T_STEPS - 1) ? (T_STEPS - 2 - s) : (T_STEPS - 1)) : s;
}

struct SmemRNN {
    float4 h4[2][K_SZ];      // 16384 B  (x,y,z = recurrences 0..2)
    float4 part[8][JPB];     //  8192 B
    float4 x4[2][JPB];       //  2048 B
    float4 stage[2][JPB];    //  2048 B
    unsigned long long bar[2];
};

__global__ void __launch_bounds__(THREADS_RNN, 1) __cluster_dims__(CLUSTER_N, 1, 1)
rnn_kernel(const float* __restrict__ Wh,
           float* __restrict__ out,
           int writeHt) {
    __shared__ SmemRNN sm;
    cg::cluster_group cluster = cg::this_cluster();
    const int rank = (int)cluster.block_rank();
    const int cid  = blockIdx.x / CLUSTER_N;
    const int tid  = threadIdx.x;
    const int lane = tid & 31;
    const int seg  = tid >> 5;          // warp id 0..7
    const int jg   = rank * JPB;

    const int r0 = cid * 3, r1 = r0 + 1, r2 = r0 + 2;
    const int g0 = r0 >> 1, d0 = r0 & 1;
    const int g1 = r1 >> 1, d1 = r1 & 1;
    const int g2 = r2 >> 1, d2 = r2 & 1;

    if (tid == 0) {
        MBARRIER_INIT(s2u(&sm.bar[0]), 1);
        MBARRIER_INIT(s2u(&sm.bar[1]), 1);
    }

    // ---- weights into registers ----
    float wa[64], wb[64];
    {
        const float* base = Wh + (size_t)(seg * 64) * K_SZ + jg + lane;
        #pragma unroll
        for (int ii = 0; ii < 64; ii++) {
            wa[ii] = base[(size_t)ii * K_SZ];
            wb[ii] = base[(size_t)ii * K_SZ + 32];
        }
    }
    // h0 = 0
    for (int i = tid; i < K_SZ; i += THREADS_RNN)
        sm.h4[0][i] = make_float4(0.f, 0.f, 0.f, 0.f);
    // x prefetch for step 0
    if (tid >= 64 && tid < 128) {
        int jj = tid - 64;
        float4 xv;
        xv.x = g_P[(size_t)g_idx[tpos(0, d0) * G_SZ + g0] * K_SZ + jg + jj];
        xv.y = g_P[(size_t)g_idx[tpos(0, d1) * G_SZ + g1] * K_SZ + jg + jj];
        xv.z = g_P[(size_t)g_idx[tpos(0, d2) * G_SZ + g2] * K_SZ + jg + jj];
        xv.w = 0.f;
        sm.x4[0][jj] = xv;
    }
    __syncthreads();
    cluster.sync();   // once: all barriers initialized cluster-wide

    // precomputed addresses
    const uint32_t my_h4    = s2u(&sm.h4[0][0]);
    const uint32_t my_bar0  = s2u(&sm.bar[0]);
    const uint32_t my_bar1  = s2u(&sm.bar[1]);
    const uint32_t my_stage = s2u(&sm.stage[0][0]);
    uint32_t rem_h4 = 0, rem_bar0 = 0, rem_bar1 = 0;
    if (tid < 8) {
        asm("mapa.shared::cluster.u32 %0, %1, %2;" : "=r"(rem_h4)   : "r"(my_h4),   "r"(tid));
        asm("mapa.shared::cluster.u32 %0, %1, %2;" : "=r"(rem_bar0) : "r"(my_bar0), "r"(tid));
        asm("mapa.shared::cluster.u32 %0, %1, %2;" : "=r"(rem_bar1) : "r"(my_bar1), "r"(tid));
    }

    int p = 0;
    for (int s = 0; s < T_STEPS; s++) {
        // ---- phase 1: 128 columns-worth of FMAs, weights in registers ----
        const float4* hb = &sm.h4[p][seg * 64];
        float a0 = 0.f, a1 = 0.f, a2 = 0.f;
        float c0 = 0.f, c1 = 0.f, c2 = 0.f;
        #pragma unroll
        for (int ii = 0; ii < 64; ii++) {
            float4 hv = hb[ii];                 // broadcast LDS.128
            a0 = fmaf(hv.x, wa[ii], a0);
            a1 = fmaf(hv.y, wa[ii], a1);
            a2 = fmaf(hv.z, wa[ii], a2);
            c0 = fmaf(hv.x, wb[ii], c0);
            c1 = fmaf(hv.y, wb[ii], c1);
            c2 = fmaf(hv.z, wb[ii], c2);
        }
        sm.part[seg][lane]      = make_float4(a0, a1, a2, 0.f);
        sm.part[seg][lane + 32] = make_float4(c0, c1, c2, 0.f);
        __syncthreads();

        const bool last = (s == T_STEPS - 1);
        if (tid < 64) {
            // ---- phase 2: reduce, tanh, write out, broadcast h ----
            const int j = tid;
            float s0 = 0.f, s1 = 0.f, s2 = 0.f;
            #pragma unroll
            for (int q = 0; q < 8; q++) {
                float4 v = sm.part[q][j];
                s0 += v.x; s1 += v.y; s2 += v.z;
            }
            float4 xv = sm.x4[p][j];
            float v0 = tanhf(s0 + xv.x);
            float v1 = tanhf(s1 + xv.y);
            float v2 = tanhf(s2 + xv.z);

            int t0 = tpos(s, d0), t1 = tpos(s, d1), t2 = tpos(s, d2);
            out[((size_t)t0 * G_SZ + g0) * (2 * K_SZ) + d0 * K_SZ + jg + j] = v0;
            out[((size_t)t1 * G_SZ + g1) * (2 * K_SZ) + d1 * K_SZ + jg + j] = v1;
            out[((size_t)t2 * G_SZ + g2) * (2 * K_SZ) + d2 * K_SZ + jg + j] = v2;
            if (last && writeHt) {
                size_t hb0 = (size_t)T_STEPS * G_SZ * 2 * K_SZ;
                out[hb0 + (size_t)g0 * (2 * K_SZ) + d0 * K_SZ + jg + j] = v0;
                out[hb0 + (size_t)g1 * (2 * K_SZ) + d1 * K_SZ + jg + j] = v1;
                out[hb0 + (size_t)g2 * (2 * K_SZ) + d2 * K_SZ + jg + j] = v2;
            }

            if (!last) {
                sm.stage[p][j] = make_float4(v0, v1, v2, 0.f);
                asm volatile("fence.proxy.async.shared::cta;" ::: "memory");
                asm volatile("bar.sync 1, 64;" ::: "memory");
                if (tid < 8) {
                    const int np = 1 - p;
                    if (tid == 0)
                        MBARRIER_EXPECT_TX(np ? my_bar1 : my_bar0,
                                           CLUSTER_N * JPB * 16);   // 8192 B
                    uint32_t dst = rem_h4 + (uint32_t)((np * K_SZ + jg) * 16);
                    uint32_t src = my_stage + (uint32_t)(p * JPB * 16);
                    uint32_t rb  = np ? rem_bar1 : rem_bar0;
                    asm volatile(
                        "cp.async.bulk.shared::cluster.shared::cta.mbarrier::complete_tx::bytes "
                        "[%0], [%1], %2, [%3];"
                        :: "r"(dst), "r"(src), "r"(JPB * 16), "r"(rb) : "memory");
                }
            }
        } else if (tid < 128 && !last) {
            // ---- x prefetch for step s+1 (overlapped with phase 2) ----
            int jj = tid - 64, sn = s + 1;
            float4 xv;
            xv.x = g_P[(size_t)g_idx[tpos(sn, d0) * G_SZ + g0] * K_SZ + jg + jj];
            xv.y = g_P[(size_t)g_idx[tpos(sn, d1) * G_SZ + g1] * K_SZ + jg + jj];
            xv.z = g_P[(size_t)g_idx[tpos(sn, d2) * G_SZ + g2] * K_SZ + jg + jj];
            xv.w = 0.f;
            sm.x4[1 - p][jj] = xv;
        }

        if (!last) {
            const int par = (s >> 1) & 1;
            MBARRIER_WAIT_PARITY((1 - p) ? my_bar1 : my_bar0, par);
        }
        p ^= 1;
    }
}

// ---------------------------------------------------------------------------
extern "C" void kernel_launch(void* const* d_in, const int* in_sizes, int n_in,
                              void* d_out, int out_size) {
    const float* seq   = (const float*)d_in[0];  // (T, V)
    const int*   perms = (const int*)  d_in[1];  // (G, V)
    const float* We    = (const float*)d_in[2];  // (V, K)
    const float* Wx    = (const float*)d_in[3];  // (K, K)
    const float* Wh    = (const float*)d_in[4];  // (K, K)
    const float* b     = (const float*)d_in[5];  // (K,)
    float* out = (float*)d_out;
    (void)in_sizes; (void)n_in;

    long long need = (long long)T_STEPS * G_SZ * 2 * K_SZ + (long long)G_SZ * 2 * K_SZ;
    int writeHt = ((long long)out_size >= need) ? 1 : 0;

    token_kernel<<<T_STEPS, 256>>>(seq, perms);
    dim3 ggrid(K_SZ / 64, V_SZ / 64);
    gemm_P_kernel<<<ggrid, 256>>>(We, Wx, b);
    rnn_kernel<<<NBLOCKS, THREADS_RNN>>>(Wh, out, writeHt);
}

// round 3
// speedup vs baseline: 2.4372x; 1.1488x over previous
#include <cuda_runtime.h>
#include <cooperative_groups.h>
#include <cstdint>

namespace cg = cooperative_groups;

#define T_STEPS 2048
#define V_SZ    2048
#define G_SZ    24
#define K_SZ    512
#define CLUSTER_N 8
#define JPB     64              // columns of Wh per CTA
#define NCLUSTERS 16            // 16 clusters * 3 recurrences = 48
#define NBLOCKS (NCLUSTERS * CLUSTER_N)
#define THREADS_RNN 256

// ---------------- mbarrier helpers ----------------
#define MBARRIER_INIT(addr, count) \
    asm volatile("mbarrier.init.shared.b64 [%0], %1;" :: "r"((uint32_t)(addr)), "r"((uint32_t)(count)) : "memory")

#define MBARRIER_EXPECT_TX(addr, bytes) \
    asm volatile("mbarrier.arrive.expect_tx.shared.b64 _, [%0], %1;" :: "r"((uint32_t)(addr)), "r"((uint32_t)(bytes)) : "memory")

#define MBARRIER_WAIT_PARITY(mbar_smem_addr, phase_parity) do { \
    uint32_t _mbar = (uint32_t)(mbar_smem_addr); \
    uint32_t _parity = (uint32_t)(phase_parity); \
    uint32_t _done; \
    asm volatile( \
        "{\n\t" \
        ".reg .pred p;\n\t" \
        "mbarrier.try_wait.parity.acquire.cta.shared::cta.b64 p, [%1], %2;\n\t" \
        "selp.b32 %0, 1, 0, p;\n\t" \
        "}" \
        : "=r"(_done) : "r"(_mbar), "r"(_parity) : "memory"); \
    if (!_done) { \
        asm volatile( \
            "{\n\t" \
            ".reg .pred P1;\n\t" \
            "WAIT_LOOP_%=:\n\t" \
            "mbarrier.try_wait.parity.acquire.cta.shared::cta.b64 P1, [%0], %1, 0x989680;\n\t" \
            "@P1 bra.uni WAIT_DONE_%=;\n\t" \
            "bra.uni WAIT_LOOP_%=;\n\t" \
            "WAIT_DONE_%=:\n\t" \
            "}" \
            :: "r"(_mbar), "r"(_parity) : "memory"); \
    } \
} while(0)

__device__ __forceinline__ uint32_t s2u(const void* p) {
    uint32_t a;
    asm("{ .reg .u64 t; cvta.to.shared.u64 t, %1; cvt.u32.u64 %0, t; }" : "=r"(a) : "l"(p));
    return a;
}

__device__ __forceinline__ void ffma2(unsigned long long& acc,
                                      unsigned long long h2,
                                      unsigned long long w2) {
    asm("fma.rn.f32x2 %0, %1, %2, %0;" : "+l"(acc) : "l"(h2), "l"(w2));
}

__device__ __forceinline__ unsigned long long packf2(float lo, float hi) {
    unsigned long long r;
    asm("mov.b64 %0, {%1, %2};" : "=l"(r) : "f"(lo), "f"(hi));
    return r;
}

__device__ __forceinline__ float sum2(unsigned long long acc) {
    float lo, hi;
    asm("mov.b64 {%0, %1}, %2;" : "=f"(lo), "=f"(hi) : "l"(acc));
    return lo + hi;
}

// Scratch (no cudaMalloc allowed)
__device__ float g_P[V_SZ * K_SZ];       // P = W_e @ Wx + b   (V, K)
__device__ int   g_idx[T_STEPS * G_SZ];  // idx[t,g] = perms[g, token_t]

// ---------------------------------------------------------------------------
// Kernel 1: recover tokens from one-hot rows, build gather index table
// ---------------------------------------------------------------------------
__global__ void token_kernel(const float* __restrict__ seq,
                             const int* __restrict__ perms) {
    int t = blockIdx.x;
    __shared__ int tok;
    const float* row = seq + (size_t)t * V_SZ;
    for (int v = threadIdx.x; v < V_SZ; v += blockDim.x)
        if (row[v] > 0.5f) tok = v;
    __syncthreads();
    if (threadIdx.x < G_SZ)
        g_idx[t * G_SZ + threadIdx.x] = perms[threadIdx.x * V_SZ + tok];
}

// ---------------------------------------------------------------------------
// Kernel 2: P = W_e @ Wx + b  (2048x512 @ 512x512)
// ---------------------------------------------------------------------------
__global__ void __launch_bounds__(256)
gemm_P_kernel(const float* __restrict__ We,
              const float* __restrict__ Wx,
              const float* __restrict__ b) {
    __shared__ float sA[64][17];
    __shared__ float sB[16][68];
    int tid = threadIdx.x;
    int tx = tid & 15, ty = tid >> 4;
    int row0 = blockIdx.y * 64;
    int col0 = blockIdx.x * 64;
    float acc[4][4] = {};

    for (int kc = 0; kc < K_SZ; kc += 16) {
        {
            int v  = tid >> 2;
            int c4 = (tid & 3) * 4;
            float4 av = *(const float4*)&We[(size_t)(row0 + v) * K_SZ + kc + c4];
            sA[v][c4 + 0] = av.x; sA[v][c4 + 1] = av.y;
            sA[v][c4 + 2] = av.z; sA[v][c4 + 3] = av.w;
        }
        {
            int c  = tid >> 4;
            int k4 = (tid & 15) * 4;
            float4 bv = *(const float4*)&Wx[(size_t)(kc + c) * K_SZ + col0 + k4];
            sB[c][k4 + 0] = bv.x; sB[c][k4 + 1] = bv.y;
            sB[c][k4 + 2] = bv.z; sB[c][k4 + 3] = bv.w;
        }
        __syncthreads();
        #pragma unroll
        for (int cc = 0; cc < 16; cc++) {
            float ar[4], br[4];
            #pragma unroll
            for (int u = 0; u < 4; u++) ar[u] = sA[ty * 4 + u][cc];
            #pragma unroll
            for (int w = 0; w < 4; w++) br[w] = sB[cc][tx * 4 + w];
            #pragma unroll
            for (int u = 0; u < 4; u++)
                #pragma unroll
                for (int w = 0; w < 4; w++)
                    acc[u][w] = fmaf(ar[u], br[w], acc[u][w]);
        }
        __syncthreads();
    }
    #pragma unroll
    for (int u = 0; u < 4; u++) {
        int r = row0 + ty * 4 + u;
        #pragma unroll
        for (int w = 0; w < 4; w++) {
            int c = col0 + tx * 4 + w;
            g_P[(size_t)r * K_SZ + c] = acc[u][w] + b[c];
        }
    }
}

// ---------------------------------------------------------------------------
// Kernel 3: persistent cluster recurrence.
//  - Wh in registers as packed f32x2 row-pairs; fma.rn.f32x2 mainloop.
//  - h stored SoA: h[buf][srcRank][rec][64]; warp seg consumes block seg only.
//  - per-(buf, srcRank) mbarriers: each warp waits only for ITS 768B slice.
// ---------------------------------------------------------------------------
__device__ __forceinline__ int tpos(int s, int dir) {
    return dir ? ((s < T_STEPS - 1) ? (T_STEPS - 2 - s) : (T_STEPS - 1)) : s;
}

struct SmemRNN {
    float  h[2][CLUSTER_N][3][64];   // 12288 B  [buf][srcRank][rec][col]
    float4 part[2][8][64];           // 16384 B
    float4 x4[2][64];                //  2048 B
    float  stage[2][3][64];          //  1536 B
    unsigned long long bar[2][CLUSTER_N];  // 128 B
};

__global__ void __launch_bounds__(THREADS_RNN, 1) __cluster_dims__(CLUSTER_N, 1, 1)
rnn_kernel(const float* __restrict__ Wh,
           float* __restrict__ out,
           int writeHt) {
    __shared__ SmemRNN sm;
    cg::cluster_group cluster = cg::this_cluster();
    const int rank = (int)cluster.block_rank();
    const int cid  = blockIdx.x / CLUSTER_N;
    const int tid  = threadIdx.x;
    const int lane = tid & 31;
    const int seg  = tid >> 5;          // warp id 0..7 == consumed srcRank
    const int jg   = rank * JPB;

    const int r0 = cid * 3, r1 = r0 + 1, r2 = r0 + 2;
    const int g0 = r0 >> 1, d0 = r0 & 1;
    const int g1 = r1 >> 1, d1 = r1 & 1;
    const int g2 = r2 >> 1, d2 = r2 & 1;

    const uint32_t bar_base = s2u(&sm.bar[0][0]);

    if (tid < CLUSTER_N) {
        MBARRIER_INIT(bar_base + (0 * CLUSTER_N + tid) * 8, 1);
        MBARRIER_INIT(bar_base + (1 * CLUSTER_N + tid) * 8, 1);
    }
    __syncthreads();
    if (tid < CLUSTER_N) {   // arm both buffers for their first use
        MBARRIER_EXPECT_TX(bar_base + (0 * CLUSTER_N + tid) * 8, 3 * 64 * 4);
        MBARRIER_EXPECT_TX(bar_base + (1 * CLUSTER_N + tid) * 8, 3 * 64 * 4);
    }

    // ---- weights into registers, packed as f32x2 row-pairs ----
    // thread (seg, lane): rows [seg*64, seg*64+64), cols jg+lane, jg+lane+32
    unsigned long long wa2[32], wb2[32];
    {
        const float* base = Wh + (size_t)(seg * 64) * K_SZ + jg + lane;
        #pragma unroll
        for (int ii = 0; ii < 32; ii++) {
            float a_lo = base[(size_t)(2 * ii) * K_SZ];
            float a_hi = base[(size_t)(2 * ii + 1) * K_SZ];
            float b_lo = base[(size_t)(2 * ii) * K_SZ + 32];
            float b_hi = base[(size_t)(2 * ii + 1) * K_SZ + 32];
            wa2[ii] = packf2(a_lo, a_hi);
            wb2[ii] = packf2(b_lo, b_hi);
        }
    }
    // h0 = 0 (buffer 0)
    for (int i = tid; i < CLUSTER_N * 3 * 64; i += THREADS_RNN)
        (&sm.h[0][0][0][0])[i] = 0.f;
    // x prefetch for step 0
    if (tid >= 64 && tid < 128) {
        int jj = tid - 64;
        sm.x4[0][jj] = make_float4(
            g_P[(size_t)g_idx[tpos(0, d0) * G_SZ + g0] * K_SZ + jg + jj],
            g_P[(size_t)g_idx[tpos(0, d1) * G_SZ + g1] * K_SZ + jg + jj],
            g_P[(size_t)g_idx[tpos(0, d2) * G_SZ + g2] * K_SZ + jg + jj],
            0.f);
    }
    __syncthreads();
    cluster.sync();   // barriers initialized & armed cluster-wide

    // remote addresses for the broadcast (thread i handles destination CTA i)
    const uint32_t my_h     = s2u(&sm.h[0][0][0][0]);
    const uint32_t my_stage = s2u(&sm.stage[0][0][0]);
    uint32_t rem_h = 0, rem_bar = 0;
    if (tid < CLUSTER_N) {
        asm("mapa.shared::cluster.u32 %0, %1, %2;" : "=r"(rem_h)   : "r"(my_h),     "r"(tid));
        asm("mapa.shared::cluster.u32 %0, %1, %2;" : "=r"(rem_bar) : "r"(bar_base), "r"(tid));
    }
    const uint32_t my_bar_seg0 = bar_base + (0 * CLUSTER_N + seg) * 8;
    const uint32_t my_bar_seg1 = bar_base + (1 * CLUSTER_N + seg) * 8;

    int par0 = 0, par1 = 0;   // parity per buffer for THIS warp's barrier
    int p = 0;
    for (int s = 0; s < T_STEPS; s++) {
        // ---- data wait: only this warp's 768B slice (skip step 0) ----
        if (s > 0) {
            if (p == 0) {
                MBARRIER_WAIT_PARITY(my_bar_seg0, par0);
                if (lane == 0) MBARRIER_EXPECT_TX(my_bar_seg0, 3 * 64 * 4);
                par0 ^= 1;
            } else {
                MBARRIER_WAIT_PARITY(my_bar_seg1, par1);
                if (lane == 0) MBARRIER_EXPECT_TX(my_bar_seg1, 3 * 64 * 4);
                par1 ^= 1;
            }
        }

        // ---- phase 1: packed f32x2 FMAs over this warp's 64-row block ----
        const float* hr = &sm.h[p][seg][0][0];
        unsigned long long A0 = 0ull, A1 = 0ull, A2 = 0ull;
        unsigned long long C0 = 0ull, C1 = 0ull, C2 = 0ull;
        #pragma unroll
        for (int ii = 0; ii < 32; ii++) {
            unsigned long long h0 = *(const unsigned long long*)(hr + 0 * 64 + 2 * ii);
            unsigned long long h1 = *(const unsigned long long*)(hr + 1 * 64 + 2 * ii);
            unsigned long long h2 = *(const unsigned long long*)(hr + 2 * 64 + 2 * ii);
            ffma2(A0, h0, wa2[ii]);
            ffma2(A1, h1, wa2[ii]);
            ffma2(A2, h2, wa2[ii]);
            ffma2(C0, h0, wb2[ii]);
            ffma2(C1, h1, wb2[ii]);
            ffma2(C2, h2, wb2[ii]);
        }
        sm.part[p][seg][lane]      = make_float4(sum2(A0), sum2(A1), sum2(A2), 0.f);
        sm.part[p][seg][lane + 32] = make_float4(sum2(C0), sum2(C1), sum2(C2), 0.f);
        __syncthreads();

        const bool last = (s == T_STEPS - 1);
        if (tid < 64) {
            // ---- phase 2: reduce, tanh, broadcast, then global stores ----
            const int j = tid;
            float s0 = 0.f, s1 = 0.f, s2 = 0.f;
            #pragma unroll
            for (int q = 0; q < 8; q++) {
                float4 v = sm.part[p][q][j];
                s0 += v.x; s1 += v.y; s2 += v.z;
            }
            float4 xv = sm.x4[p][j];
            float v0 = tanhf(s0 + xv.x);
            float v1 = tanhf(s1 + xv.y);
            float v2 = tanhf(s2 + xv.z);

            if (!last) {
                sm.stage[p][0][j] = v0;
                sm.stage[p][1][j] = v1;
                sm.stage[p][2][j] = v2;
                asm volatile("fence.proxy.async.shared::cta;" ::: "memory");
                asm volatile("bar.sync 1, 64;" ::: "memory");
                if (tid < CLUSTER_N) {
                    const int np = 1 - p;
                    uint32_t dst = rem_h + (uint32_t)((np * CLUSTER_N + rank) * 3 * 64 * 4);
                    uint32_t src = my_stage + (uint32_t)(p * 3 * 64 * 4);
                    uint32_t rb  = rem_bar + (uint32_t)((np * CLUSTER_N + rank) * 8);
                    asm volatile(
                        "cp.async.bulk.shared::cluster.shared::cta.mbarrier::complete_tx::bytes "
                        "[%0], [%1], %2, [%3];"
                        :: "r"(dst), "r"(src), "r"(3 * 64 * 4), "r"(rb) : "memory");
                }
            }

            int t0 = tpos(s, d0), t1 = tpos(s, d1), t2 = tpos(s, d2);
            out[((size_t)t0 * G_SZ + g0) * (2 * K_SZ) + d0 * K_SZ + jg + j] = v0;
            out[((size_t)t1 * G_SZ + g1) * (2 * K_SZ) + d1 * K_SZ + jg + j] = v1;
            out[((size_t)t2 * G_SZ + g2) * (2 * K_SZ) + d2 * K_SZ + jg + j] = v2;
            if (last && writeHt) {
                size_t hb0 = (size_t)T_STEPS * G_SZ * 2 * K_SZ;
                out[hb0 + (size_t)g0 * (2 * K_SZ) + d0 * K_SZ + jg + j] = v0;
                out[hb0 + (size_t)g1 * (2 * K_SZ) + d1 * K_SZ + jg + j] = v1;
                out[hb0 + (size_t)g2 * (2 * K_SZ) + d2 * K_SZ + jg + j] = v2;
            }
        } else if (tid < 128 && !last) {
            // ---- x prefetch for step s+1 (overlapped with phase 2) ----
            int jj = tid - 64, sn = s + 1;
            sm.x4[1 - p][jj] = make_float4(
                g_P[(size_t)g_idx[tpos(sn, d0) * G_SZ + g0] * K_SZ + jg + jj],
                g_P[(size_t)g_idx[tpos(sn, d1) * G_SZ + g1] * K_SZ + jg + jj],
                g_P[(size_t)g_idx[tpos(sn, d2) * G_SZ + g2] * K_SZ + jg + jj],
                0.f);
        }
        p ^= 1;
    }
}

// ---------------------------------------------------------------------------
extern "C" void kernel_launch(void* const* d_in, const int* in_sizes, int n_in,
                              void* d_out, int out_size) {
    const float* seq   = (const float*)d_in[0];  // (T, V)
    const int*   perms = (const int*)  d_in[1];  // (G, V)
    const float* We    = (const float*)d_in[2];  // (V, K)
    const float* Wx    = (const float*)d_in[3];  // (K, K)
    const float* Wh    = (const float*)d_in[4];  // (K, K)
    const float* b     = (const float*)d_in[5];  // (K,)
    float* out = (float*)d_out;
    (void)in_sizes; (void)n_in;

    long long need = (long long)T_STEPS * G_SZ * 2 * K_SZ + (long long)G_SZ * 2 * K_SZ;
    int writeHt = ((long long)out_size >= need) ? 1 : 0;

    token_kernel<<<T_STEPS, 256>>>(seq, perms);
    dim3 ggrid(K_SZ / 64, V_SZ / 64);
    gemm_P_kernel<<<ggrid, 256>>>(We, Wx, b);
    rnn_kernel<<<NBLOCKS, THREADS_RNN>>>(Wh, out, writeHt);
}